// round 1
// baseline (speedup 1.0000x reference)
#include <cuda_runtime.h>
#include <cstdint>

#define N_USER  100000
#define N_PHOTO 200000
#define K_IN    256
#define N_OUT   64

// Scratch: projected features + degree counts (static device globals; no allocs).
__device__ float g_Wh_user [(size_t)N_USER  * N_OUT];   // 25.6 MB
__device__ float g_Wh_photo[(size_t)N_PHOTO * N_OUT];   // 51.2 MB
__device__ float g_deg_user [N_USER];
__device__ float g_deg_photo[N_PHOTO];

// ---------------------------------------------------------------------------
// C[M,64] = A[M,256] @ W[256,64] + bias
// Block tile: 128 rows x 64 cols, 128 threads, each thread 8x8 outputs.
// ---------------------------------------------------------------------------
__global__ __launch_bounds__(128) void gemm_bias_kernel(
    const float* __restrict__ A, const float* __restrict__ W,
    const float* __restrict__ bias, float* __restrict__ C, int M)
{
    constexpr int BM = 128, BK = 16;
    __shared__ float As[BK][BM];      // transposed A tile: As[k][row]
    __shared__ float Ws[BK][N_OUT];   // W tile: Ws[k][n]

    const int tid = threadIdx.x;
    const int tc = tid & 7;    // column group: cols tc*8 .. tc*8+7
    const int tr = tid >> 3;   // row group:    rows tr*8 .. tr*8+7
    const int rowBase = blockIdx.x * BM;

    float acc[8][8];
#pragma unroll
    for (int i = 0; i < 8; i++)
#pragma unroll
        for (int j = 0; j < 8; j++) acc[i][j] = 0.f;

    for (int k0 = 0; k0 < K_IN; k0 += BK) {
        // Load A tile: 128 rows x 16 k-cols = 512 float4, 4 per thread.
#pragma unroll
        for (int it = 0; it < 4; it++) {
            int idx = it * 128 + tid;
            int row = idx >> 2;
            int c   = idx & 3;
            int g   = rowBase + row;
            float4 v = make_float4(0.f, 0.f, 0.f, 0.f);
            if (g < M)
                v = *(const float4*)&A[(size_t)g * K_IN + k0 + c * 4];
            As[c * 4 + 0][row] = v.x;
            As[c * 4 + 1][row] = v.y;
            As[c * 4 + 2][row] = v.z;
            As[c * 4 + 3][row] = v.w;
        }
        // Load W tile: 16 x 64 = 256 float4, 2 per thread (coalesced).
#pragma unroll
        for (int it = 0; it < 2; it++) {
            int idx = it * 128 + tid;
            int kk = idx >> 4;
            int nn = idx & 15;
            *(float4*)&Ws[kk][nn * 4] =
                *(const float4*)&W[(size_t)(k0 + kk) * N_OUT + nn * 4];
        }
        __syncthreads();

#pragma unroll
        for (int k = 0; k < BK; k++) {
            float4 a0 = *(const float4*)&As[k][tr * 8];
            float4 a1 = *(const float4*)&As[k][tr * 8 + 4];
            float4 w0 = *(const float4*)&Ws[k][tc * 8];
            float4 w1 = *(const float4*)&Ws[k][tc * 8 + 4];
            float a[8] = {a0.x, a0.y, a0.z, a0.w, a1.x, a1.y, a1.z, a1.w};
            float w[8] = {w0.x, w0.y, w0.z, w0.w, w1.x, w1.y, w1.z, w1.w};
#pragma unroll
            for (int i = 0; i < 8; i++)
#pragma unroll
                for (int j = 0; j < 8; j++)
                    acc[i][j] = fmaf(a[i], w[j], acc[i][j]);
        }
        __syncthreads();
    }

    float bw[8];
#pragma unroll
    for (int j = 0; j < 8; j++) bw[j] = bias[tc * 8 + j];

#pragma unroll
    for (int i = 0; i < 8; i++) {
        int g = rowBase + tr * 8 + i;
        if (g < M) {
            float4 o0 = make_float4(acc[i][0] + bw[0], acc[i][1] + bw[1],
                                    acc[i][2] + bw[2], acc[i][3] + bw[3]);
            float4 o1 = make_float4(acc[i][4] + bw[4], acc[i][5] + bw[5],
                                    acc[i][6] + bw[6], acc[i][7] + bw[7]);
            *(float4*)&C[(size_t)g * N_OUT + tc * 8]     = o0;
            *(float4*)&C[(size_t)g * N_OUT + tc * 8 + 4] = o1;
        }
    }
}

// ---------------------------------------------------------------------------
// Edge scatter: 16 threads per edge, each does one 16B vector RED (sm_90+
// red.global.add.v4.f32). Also accumulates float in-degree (1 RED per edge).
// Wh tables are L2-resident (77 MB total < 126 MB L2), so gathers are L2 hits.
// ---------------------------------------------------------------------------
__global__ __launch_bounds__(256) void scatter_kernel(
    const float* __restrict__ Wh, const int* __restrict__ src,
    const int* __restrict__ dst, float* __restrict__ out,
    float* __restrict__ deg, int E)
{
    int t = blockIdx.x * 256 + threadIdx.x;
    int e = t >> 4;
    if (e >= E) return;
    int lane = t & 15;
    int s = src[e];
    int d = dst[e];
    float4 v = ((const float4*)(Wh + (size_t)s * N_OUT))[lane];
    float4* p = ((float4*)(out + (size_t)d * N_OUT)) + lane;
    asm volatile("red.global.add.v4.f32 [%0], {%1,%2,%3,%4};"
                 :: "l"(p), "f"(v.x), "f"(v.y), "f"(v.z), "f"(v.w)
                 : "memory");
    if (lane == 0) atomicAdd(&deg[d], 1.0f);
}

// ---------------------------------------------------------------------------
// out[node][:] /= max(deg[node], 1)   (deg==0 nodes stay 0, matching ref)
// ---------------------------------------------------------------------------
__global__ __launch_bounds__(256) void finalize_kernel(
    float* __restrict__ out, const float* __restrict__ deg, int n)
{
    int t = blockIdx.x * 256 + threadIdx.x;
    if (t >= n * 16) return;
    int node = t >> 4;
    int lane = t & 15;
    float d = deg[node];
    float inv = (d > 1.0f) ? (1.0f / d) : 1.0f;
    float4* p = ((float4*)(out + (size_t)node * N_OUT)) + lane;
    float4 v = *p;
    v.x *= inv; v.y *= inv; v.z *= inv; v.w *= inv;
    *p = v;
}

// ---------------------------------------------------------------------------
extern "C" void kernel_launch(void* const* d_in, const int* in_sizes, int n_in,
                              void* d_out, int out_size)
{
    const float* user_feats  = (const float*)d_in[0];
    const float* photo_feats = (const float*)d_in[1];
    const float* W_likes     = (const float*)d_in[2];
    const float* b_likes     = (const float*)d_in[3];
    const float* W_likedby   = (const float*)d_in[4];
    const float* b_likedby   = (const float*)d_in[5];
    const int*   likes_src   = (const int*)d_in[6];
    const int*   likes_dst   = (const int*)d_in[7];
    const int*   likedby_src = (const int*)d_in[8];
    const int*   likedby_dst = (const int*)d_in[9];
    const int E1 = in_sizes[6];
    const int E2 = in_sizes[8];

    float* out_user  = (float*)d_out;                            // [N_USER, 64]
    float* out_photo = (float*)d_out + (size_t)N_USER * N_OUT;   // [N_PHOTO, 64]

    float *wh_user, *wh_photo, *deg_user, *deg_photo;
    cudaGetSymbolAddress((void**)&wh_user,  g_Wh_user);
    cudaGetSymbolAddress((void**)&wh_photo, g_Wh_photo);
    cudaGetSymbolAddress((void**)&deg_user,  g_deg_user);
    cudaGetSymbolAddress((void**)&deg_photo, g_deg_photo);

    cudaMemsetAsync(d_out, 0, (size_t)out_size * sizeof(float));
    cudaMemsetAsync(deg_user,  0, (size_t)N_USER  * sizeof(float));
    cudaMemsetAsync(deg_photo, 0, (size_t)N_PHOTO * sizeof(float));

    // Per-etype projection (project-then-aggregate: 4x less edge traffic).
    gemm_bias_kernel<<<(N_USER  + 127) / 128, 128>>>(user_feats,  W_likes,   b_likes,   wh_user,  N_USER);
    gemm_bias_kernel<<<(N_PHOTO + 127) / 128, 128>>>(photo_feats, W_likedby, b_likedby, wh_photo, N_PHOTO);

    // Edge aggregation (copy_u + sum), degrees alongside.
    scatter_kernel<<<((size_t)E1 * 16 + 255) / 256, 256>>>(wh_user,  likes_src,   likes_dst,   out_photo, deg_photo, E1);
    scatter_kernel<<<((size_t)E2 * 16 + 255) / 256, 256>>>(wh_photo, likedby_src, likedby_dst, out_user,  deg_user,  E2);

    // Mean (sum / max(deg,1)).
    finalize_kernel<<<((size_t)N_USER  * 16 + 255) / 256, 256>>>(out_user,  deg_user,  N_USER);
    finalize_kernel<<<((size_t)N_PHOTO * 16 + 255) / 256, 256>>>(out_photo, deg_photo, N_PHOTO);
}

// round 2
// speedup vs baseline: 1.0960x; 1.0960x over previous
#include <cuda_runtime.h>
#include <cstdint>

#define N_USER  100000
#define N_PHOTO 200000
#define K_IN    256
#define N_OUT   64

typedef unsigned long long ull;

// Scratch: projected features + degree counts (static device globals; no allocs).
__device__ float g_Wh_user [(size_t)N_USER  * N_OUT];   // 25.6 MB
__device__ float g_Wh_photo[(size_t)N_PHOTO * N_OUT];   // 51.2 MB
__device__ float g_deg_user [N_USER];
__device__ float g_deg_photo[N_PHOTO];

// ---- packed f32x2 helpers (Blackwell FFMA2 — only reachable via PTX) ------
__device__ __forceinline__ ull pack2(float lo, float hi) {
    ull r;
    asm("mov.b64 %0, {%1, %2};" : "=l"(r) : "f"(lo), "f"(hi));
    return r;
}
__device__ __forceinline__ ull fma2(ull a, ull b, ull c) {
    ull d;
    asm("fma.rn.f32x2 %0, %1, %2, %3;" : "=l"(d) : "l"(a), "l"(b), "l"(c));
    return d;
}
__device__ __forceinline__ void unpack2(ull v, float& lo, float& hi) {
    asm("mov.b64 {%0, %1}, %2;" : "=f"(lo), "=f"(hi) : "l"(v));
}

// ---------------------------------------------------------------------------
// C[M,64] = A[M,256] @ W[256,64] + bias
// Block tile 128x64, 128 threads, thread tile 8x8 computed as 8x4 f32x2 pairs
// (pairs along columns). Inner loop = 32 FFMA2 per k → 2x the 3-reg FFMA rate.
// ---------------------------------------------------------------------------
__global__ __launch_bounds__(128) void gemm_bias_kernel(
    const float* __restrict__ A, const float* __restrict__ W,
    const float* __restrict__ bias, float* __restrict__ C, int M)
{
    constexpr int BM = 128, BK = 16;
    __shared__ float As[BK][BM];      // transposed A tile: As[k][row]
    __shared__ float Ws[BK][N_OUT];   // W tile: Ws[k][n]

    const int tid = threadIdx.x;
    const int tc = tid & 7;    // column group: cols tc*8 .. tc*8+7
    const int tr = tid >> 3;   // row group:    rows tr*8 .. tr*8+7
    const int rowBase = blockIdx.x * BM;

    ull acc[8][4];
#pragma unroll
    for (int i = 0; i < 8; i++)
#pragma unroll
        for (int j = 0; j < 4; j++) acc[i][j] = 0ULL;

    for (int k0 = 0; k0 < K_IN; k0 += BK) {
        // Load A tile: 128 rows x 16 k-cols = 512 float4, 4 per thread.
#pragma unroll
        for (int it = 0; it < 4; it++) {
            int idx = it * 128 + tid;
            int row = idx >> 2;
            int c   = idx & 3;
            int g   = rowBase + row;
            float4 v = make_float4(0.f, 0.f, 0.f, 0.f);
            if (g < M)
                v = *(const float4*)&A[(size_t)g * K_IN + k0 + c * 4];
            As[c * 4 + 0][row] = v.x;
            As[c * 4 + 1][row] = v.y;
            As[c * 4 + 2][row] = v.z;
            As[c * 4 + 3][row] = v.w;
        }
        // Load W tile: 16 x 64 = 256 float4, 2 per thread (coalesced).
#pragma unroll
        for (int it = 0; it < 2; it++) {
            int idx = it * 128 + tid;
            int kk = idx >> 4;
            int nn = idx & 15;
            *(float4*)&Ws[kk][nn * 4] =
                *(const float4*)&W[(size_t)(k0 + kk) * N_OUT + nn * 4];
        }
        __syncthreads();

#pragma unroll
        for (int k = 0; k < BK; k++) {
            float4 a0 = *(const float4*)&As[k][tr * 8];
            float4 a1 = *(const float4*)&As[k][tr * 8 + 4];
            // w pairs come packed straight out of smem (8B-aligned).
            const ull* wp = (const ull*)&Ws[k][tc * 8];
            ull w2[4];
#pragma unroll
            for (int j = 0; j < 4; j++) w2[j] = wp[j];
            ull a2[8];
            a2[0] = pack2(a0.x, a0.x); a2[1] = pack2(a0.y, a0.y);
            a2[2] = pack2(a0.z, a0.z); a2[3] = pack2(a0.w, a0.w);
            a2[4] = pack2(a1.x, a1.x); a2[5] = pack2(a1.y, a1.y);
            a2[6] = pack2(a1.z, a1.z); a2[7] = pack2(a1.w, a1.w);
#pragma unroll
            for (int i = 0; i < 8; i++)
#pragma unroll
                for (int j = 0; j < 4; j++)
                    acc[i][j] = fma2(a2[i], w2[j], acc[i][j]);
        }
        __syncthreads();
    }

    float bw[8];
#pragma unroll
    for (int j = 0; j < 8; j++) bw[j] = bias[tc * 8 + j];

#pragma unroll
    for (int i = 0; i < 8; i++) {
        int g = rowBase + tr * 8 + i;
        if (g < M) {
            float o[8];
#pragma unroll
            for (int j = 0; j < 4; j++)
                unpack2(acc[i][j], o[2 * j], o[2 * j + 1]);
            float4 o0 = make_float4(o[0] + bw[0], o[1] + bw[1],
                                    o[2] + bw[2], o[3] + bw[3]);
            float4 o1 = make_float4(o[4] + bw[4], o[5] + bw[5],
                                    o[6] + bw[6], o[7] + bw[7]);
            *(float4*)&C[(size_t)g * N_OUT + tc * 8]     = o0;
            *(float4*)&C[(size_t)g * N_OUT + tc * 8 + 4] = o1;
        }
    }
}

// ---------------------------------------------------------------------------
// In-degree accumulation (float counts, matching the reference's fp32 deg).
// ---------------------------------------------------------------------------
__global__ __launch_bounds__(256) void degree_kernel(
    const int* __restrict__ dst, float* __restrict__ deg, int E)
{
    int e = blockIdx.x * 256 + threadIdx.x;
    if (e < E) atomicAdd(&deg[dst[e]], 1.0f);
}

// ---------------------------------------------------------------------------
// Edge scatter with mean folded in: out[d] += Wh[s] * (1/deg[d]).
// 16 threads per edge-lane, 2 edges per thread (e and e+half) for MLP.
// red.global.add.v4.f32: one 16B vector RED per edge-lane.
// ---------------------------------------------------------------------------
__global__ __launch_bounds__(256) void scatter_mean_kernel(
    const float* __restrict__ Wh, const int* __restrict__ src,
    const int* __restrict__ dst, const float* __restrict__ deg,
    float* __restrict__ out, int E)
{
    const int half = (E + 1) >> 1;
    int t = blockIdx.x * 256 + threadIdx.x;
    int e0 = t >> 4;
    if (e0 >= half) return;
    int lane = t & 15;
    int e1 = e0 + half;
    bool has1 = (e1 < E);

    int s0 = __ldg(&src[e0]);
    int d0 = __ldg(&dst[e0]);
    int s1 = has1 ? __ldg(&src[e1]) : s0;
    int d1 = has1 ? __ldg(&dst[e1]) : d0;

    // two independent gathers in flight
    float4 v0 = __ldg(((const float4*)(Wh + (size_t)s0 * N_OUT)) + lane);
    float4 v1 = __ldg(((const float4*)(Wh + (size_t)s1 * N_OUT)) + lane);
    float inv0 = __frcp_rn(__ldg(&deg[d0]));
    float inv1 = __frcp_rn(__ldg(&deg[d1]));

    v0.x *= inv0; v0.y *= inv0; v0.z *= inv0; v0.w *= inv0;
    float4* p0 = ((float4*)(out + (size_t)d0 * N_OUT)) + lane;
    asm volatile("red.global.add.v4.f32 [%0], {%1,%2,%3,%4};"
                 :: "l"(p0), "f"(v0.x), "f"(v0.y), "f"(v0.z), "f"(v0.w)
                 : "memory");
    if (has1) {
        v1.x *= inv1; v1.y *= inv1; v1.z *= inv1; v1.w *= inv1;
        float4* p1 = ((float4*)(out + (size_t)d1 * N_OUT)) + lane;
        asm volatile("red.global.add.v4.f32 [%0], {%1,%2,%3,%4};"
                     :: "l"(p1), "f"(v1.x), "f"(v1.y), "f"(v1.z), "f"(v1.w)
                     : "memory");
    }
}

// ---------------------------------------------------------------------------
extern "C" void kernel_launch(void* const* d_in, const int* in_sizes, int n_in,
                              void* d_out, int out_size)
{
    const float* user_feats  = (const float*)d_in[0];
    const float* photo_feats = (const float*)d_in[1];
    const float* W_likes     = (const float*)d_in[2];
    const float* b_likes     = (const float*)d_in[3];
    const float* W_likedby   = (const float*)d_in[4];
    const float* b_likedby   = (const float*)d_in[5];
    const int*   likes_src   = (const int*)d_in[6];
    const int*   likes_dst   = (const int*)d_in[7];
    const int*   likedby_src = (const int*)d_in[8];
    const int*   likedby_dst = (const int*)d_in[9];
    const int E1 = in_sizes[6];
    const int E2 = in_sizes[8];

    float* out_user  = (float*)d_out;                            // [N_USER, 64]
    float* out_photo = (float*)d_out + (size_t)N_USER * N_OUT;   // [N_PHOTO, 64]

    float *wh_user, *wh_photo, *deg_user, *deg_photo;
    cudaGetSymbolAddress((void**)&wh_user,  g_Wh_user);
    cudaGetSymbolAddress((void**)&wh_photo, g_Wh_photo);
    cudaGetSymbolAddress((void**)&deg_user,  g_deg_user);
    cudaGetSymbolAddress((void**)&deg_photo, g_deg_photo);

    cudaMemsetAsync(d_out, 0, (size_t)out_size * sizeof(float));
    cudaMemsetAsync(deg_user,  0, (size_t)N_USER  * sizeof(float));
    cudaMemsetAsync(deg_photo, 0, (size_t)N_PHOTO * sizeof(float));

    // Degrees (needed by the fused mean-scatter).
    degree_kernel<<<(E1 + 255) / 256, 256>>>(likes_dst,   deg_photo, E1);
    degree_kernel<<<(E2 + 255) / 256, 256>>>(likedby_dst, deg_user,  E2);

    // Per-etype projection (FFMA2 inner loop).
    gemm_bias_kernel<<<(N_USER  + 127) / 128, 128>>>(user_feats,  W_likes,   b_likes,   wh_user,  N_USER);
    gemm_bias_kernel<<<(N_PHOTO + 127) / 128, 128>>>(photo_feats, W_likedby, b_likedby, wh_photo, N_PHOTO);

    // Edge aggregation with mean folded in (copy_u + mean in one pass).
    {
        int h1 = (E1 + 1) >> 1;
        int h2 = (E2 + 1) >> 1;
        scatter_mean_kernel<<<((size_t)h1 * 16 + 255) / 256, 256>>>(
            wh_user,  likes_src,   likes_dst,   deg_photo, out_photo, E1);
        scatter_mean_kernel<<<((size_t)h2 * 16 + 255) / 256, 256>>>(
            wh_photo, likedby_src, likedby_dst, deg_user,  out_user,  E2);
    }
}

// round 3
// speedup vs baseline: 1.2013x; 1.0961x over previous
#include <cuda_runtime.h>
#include <cstdint>

#define N_USER  100000
#define N_PHOTO 200000
#define K_IN    256
#define N_OUT   64

typedef unsigned long long ull;

// Scratch (static device globals; no allocs).
__device__ float g_Wh_user [(size_t)N_USER  * N_OUT];   // 25.6 MB
__device__ float g_Wh_photo[(size_t)N_PHOTO * N_OUT];   // 51.2 MB
__device__ float g_deg_user [N_USER];
__device__ float g_deg_photo[N_PHOTO];

__device__ __forceinline__ unsigned f2tf32(float f) {
    unsigned r;
    asm("cvt.rna.tf32.f32 %0, %1;" : "=r"(r) : "f"(f));
    return r;
}

// ---------------------------------------------------------------------------
// Tensor-core GEMM: C[M,64] = A[M,256] @ W[256,64] + bias  (tf32 HMMA)
// CTA: 256 threads (8 warps), 256 rows. Warp w: rows w*32..w*32+31
// (two m16 subtiles sharing B fragments), all 64 cols (8 n-tiles).
// mma.sync.aligned.m16n8k8.row.col.f32.tf32.tf32.f32
//
// Smem:
//   Bsm [32 ksteps][4 t][64 n'] ull : (tf32 W[8kk+t][n], W[8kk+t+4][n]) packed,
//        n' = (n&7)*8 | (n>>3)  -> one LDS.128 = B frags of 2 adjacent n-tiles.
//   As  [32 k][264] tf32 bits, rows remapped rr = (r&~15)|((r&7)<<1)|((r>>3)&1)
//        -> (a0,a1) = one LDS.64, (a2,a3) = one LDS.64.
// ---------------------------------------------------------------------------
#define AS_STRIDE 264
#define SMEM_BYTES (65536 + 32 * AS_STRIDE * 4)   // 64KB Bsm + 33.8KB As

__global__ __launch_bounds__(256) void gemm_tc(
    const float* __restrict__ A, const float* __restrict__ W,
    const float* __restrict__ bias, float* __restrict__ C, int M)
{
    extern __shared__ char smem_raw[];
    ull*      Bsm = (ull*)smem_raw;                     // [32][4][64]
    unsigned* As  = (unsigned*)(smem_raw + 65536);      // [32][AS_STRIDE]

    const int tid  = threadIdx.x;
    const int lane = tid & 31;
    const int warp = tid >> 5;
    const int g = lane >> 2;   // 0..7
    const int t = lane & 3;    // 0..3

    // ---- build Bsm: whole W, tf32-converted, k-paired, n-digit-swapped ----
    for (int i = tid; i < 8192; i += 256) {
        int np = i & 63, tt = (i >> 6) & 3, kk = i >> 8;
        int n  = ((np & 7) << 3) | (np >> 3);
        int k1 = kk * 8 + tt;
        unsigned lo = f2tf32(W[(size_t)k1 * 64 + n]);
        unsigned hi = f2tf32(W[(size_t)(k1 + 4) * 64 + n]);
        Bsm[i] = ((ull)hi << 32) | (ull)lo;
    }

    const int rowBase = blockIdx.x * 256;
    const int myRow   = rowBase + tid;
    const bool rowOK  = myRow < M;
    const float4* Arow = (const float4*)(A + (size_t)myRow * K_IN);
    const int rr = (tid & ~15) | ((tid & 7) << 1) | ((tid >> 3) & 1);

    float acc[2][8][4];
#pragma unroll
    for (int m = 0; m < 2; m++)
#pragma unroll
        for (int j = 0; j < 8; j++)
#pragma unroll
            for (int q = 0; q < 4; q++) acc[m][j][q] = 0.f;

    // prologue: stage chunk 0 (k 0..31) into regs
    float4 st[8];
#pragma unroll
    for (int q = 0; q < 8; q++)
        st[q] = rowOK ? Arow[q] : make_float4(0.f, 0.f, 0.f, 0.f);

    for (int c = 0; c < 8; c++) {
        if (c) __syncthreads();          // readers of As done before overwrite
        // cvt + store staged chunk into As
#pragma unroll
        for (int q = 0; q < 8; q++) {
            int kl4 = q * 4;
            As[(kl4 + 0) * AS_STRIDE + rr] = f2tf32(st[q].x);
            As[(kl4 + 1) * AS_STRIDE + rr] = f2tf32(st[q].y);
            As[(kl4 + 2) * AS_STRIDE + rr] = f2tf32(st[q].z);
            As[(kl4 + 3) * AS_STRIDE + rr] = f2tf32(st[q].w);
        }
        __syncthreads();                 // also orders Bsm build before 1st use

        // prefetch next chunk (overlaps the mma work below)
        if (c < 7) {
#pragma unroll
            for (int q = 0; q < 8; q++)
                st[q] = rowOK ? Arow[(c + 1) * 8 + q]
                              : make_float4(0.f, 0.f, 0.f, 0.f);
        }

        // compute 4 ksteps of this chunk
#pragma unroll
        for (int kl = 0; kl < 4; kl++) {
            const int kk = c * 4 + kl;
            uint2 a01[2], a23[2];
#pragma unroll
            for (int m = 0; m < 2; m++) {
                int sb = warp * 32 + m * 16 + 2 * g;
                a01[m] = *(const uint2*)&As[(kl * 8 + t) * AS_STRIDE + sb];
                a23[m] = *(const uint2*)&As[(kl * 8 + t + 4) * AS_STRIDE + sb];
            }
            const uint4* bp4 =
                (const uint4*)(Bsm + ((size_t)kk * 4 + t) * 64 + g * 8);
#pragma unroll
            for (int jj = 0; jj < 4; jj++) {
                uint4 bv = bp4[jj];      // B frags for n-tiles 2jj, 2jj+1
#pragma unroll
                for (int m = 0; m < 2; m++) {
                    asm volatile(
                        "mma.sync.aligned.m16n8k8.row.col.f32.tf32.tf32.f32 "
                        "{%0,%1,%2,%3}, {%4,%5,%6,%7}, {%8,%9}, {%0,%1,%2,%3};"
                        : "+f"(acc[m][2 * jj][0]), "+f"(acc[m][2 * jj][1]),
                          "+f"(acc[m][2 * jj][2]), "+f"(acc[m][2 * jj][3])
                        : "r"(a01[m].x), "r"(a01[m].y),
                          "r"(a23[m].x), "r"(a23[m].y),
                          "r"(bv.x), "r"(bv.y));
                    asm volatile(
                        "mma.sync.aligned.m16n8k8.row.col.f32.tf32.tf32.f32 "
                        "{%0,%1,%2,%3}, {%4,%5,%6,%7}, {%8,%9}, {%0,%1,%2,%3};"
                        : "+f"(acc[m][2 * jj + 1][0]), "+f"(acc[m][2 * jj + 1][1]),
                          "+f"(acc[m][2 * jj + 1][2]), "+f"(acc[m][2 * jj + 1][3])
                        : "r"(a01[m].x), "r"(a01[m].y),
                          "r"(a23[m].x), "r"(a23[m].y),
                          "r"(bv.z), "r"(bv.w));
                }
            }
        }
    }

    // epilogue: bias + store
#pragma unroll
    for (int m = 0; m < 2; m++) {
        int r0 = rowBase + warp * 32 + m * 16 + g;
#pragma unroll
        for (int j = 0; j < 8; j++) {
            int col = j * 8 + 2 * t;
            float b0 = bias[col], b1 = bias[col + 1];
            if (r0 < M) {
                float2 v = make_float2(acc[m][j][0] + b0, acc[m][j][1] + b1);
                *(float2*)&C[(size_t)r0 * N_OUT + col] = v;
            }
            if (r0 + 8 < M) {
                float2 v = make_float2(acc[m][j][2] + b0, acc[m][j][3] + b1);
                *(float2*)&C[(size_t)(r0 + 8) * N_OUT + col] = v;
            }
        }
    }
}

// ---------------------------------------------------------------------------
// In-degree accumulation (float counts).
// ---------------------------------------------------------------------------
__global__ __launch_bounds__(256) void degree_kernel(
    const int* __restrict__ dst, float* __restrict__ deg, int E)
{
    int e = blockIdx.x * 256 + threadIdx.x;
    if (e < E) atomicAdd(&deg[dst[e]], 1.0f);
}

// ---------------------------------------------------------------------------
// Edge scatter with mean folded in: out[d] += Wh[s] * (1/deg[d]).
// 16 threads per edge-lane, 2 edges per thread for MLP; vector REDs.
// ---------------------------------------------------------------------------
__global__ __launch_bounds__(256) void scatter_mean_kernel(
    const float* __restrict__ Wh, const int* __restrict__ src,
    const int* __restrict__ dst, const float* __restrict__ deg,
    float* __restrict__ out, int E)
{
    const int half = (E + 1) >> 1;
    int t = blockIdx.x * 256 + threadIdx.x;
    int e0 = t >> 4;
    if (e0 >= half) return;
    int lane = t & 15;
    int e1 = e0 + half;
    bool has1 = (e1 < E);

    int s0 = __ldg(&src[e0]);
    int d0 = __ldg(&dst[e0]);
    int s1 = has1 ? __ldg(&src[e1]) : s0;
    int d1 = has1 ? __ldg(&dst[e1]) : d0;

    float4 v0 = __ldg(((const float4*)(Wh + (size_t)s0 * N_OUT)) + lane);
    float4 v1 = __ldg(((const float4*)(Wh + (size_t)s1 * N_OUT)) + lane);
    float inv0 = __frcp_rn(__ldg(&deg[d0]));
    float inv1 = __frcp_rn(__ldg(&deg[d1]));

    v0.x *= inv0; v0.y *= inv0; v0.z *= inv0; v0.w *= inv0;
    float4* p0 = ((float4*)(out + (size_t)d0 * N_OUT)) + lane;
    asm volatile("red.global.add.v4.f32 [%0], {%1,%2,%3,%4};"
                 :: "l"(p0), "f"(v0.x), "f"(v0.y), "f"(v0.z), "f"(v0.w)
                 : "memory");
    if (has1) {
        v1.x *= inv1; v1.y *= inv1; v1.z *= inv1; v1.w *= inv1;
        float4* p1 = ((float4*)(out + (size_t)d1 * N_OUT)) + lane;
        asm volatile("red.global.add.v4.f32 [%0], {%1,%2,%3,%4};"
                     :: "l"(p1), "f"(v1.x), "f"(v1.y), "f"(v1.z), "f"(v1.w)
                     : "memory");
    }
}

// ---------------------------------------------------------------------------
extern "C" void kernel_launch(void* const* d_in, const int* in_sizes, int n_in,
                              void* d_out, int out_size)
{
    const float* user_feats  = (const float*)d_in[0];
    const float* photo_feats = (const float*)d_in[1];
    const float* W_likes     = (const float*)d_in[2];
    const float* b_likes     = (const float*)d_in[3];
    const float* W_likedby   = (const float*)d_in[4];
    const float* b_likedby   = (const float*)d_in[5];
    const int*   likes_src   = (const int*)d_in[6];
    const int*   likes_dst   = (const int*)d_in[7];
    const int*   likedby_src = (const int*)d_in[8];
    const int*   likedby_dst = (const int*)d_in[9];
    const int E1 = in_sizes[6];
    const int E2 = in_sizes[8];

    float* out_user  = (float*)d_out;                            // [N_USER, 64]
    float* out_photo = (float*)d_out + (size_t)N_USER * N_OUT;   // [N_PHOTO, 64]

    float *wh_user, *wh_photo, *deg_user, *deg_photo;
    cudaGetSymbolAddress((void**)&wh_user,  g_Wh_user);
    cudaGetSymbolAddress((void**)&wh_photo, g_Wh_photo);
    cudaGetSymbolAddress((void**)&deg_user,  g_deg_user);
    cudaGetSymbolAddress((void**)&deg_photo, g_deg_photo);

    static bool attr_done = false;
    if (!attr_done) {
        cudaFuncSetAttribute(gemm_tc,
                             cudaFuncAttributeMaxDynamicSharedMemorySize,
                             SMEM_BYTES);
        attr_done = true;
    }

    cudaMemsetAsync(d_out, 0, (size_t)out_size * sizeof(float));
    cudaMemsetAsync(deg_user,  0, (size_t)N_USER  * sizeof(float));
    cudaMemsetAsync(deg_photo, 0, (size_t)N_PHOTO * sizeof(float));

    // Degrees (needed by the fused mean-scatter).
    degree_kernel<<<(E1 + 255) / 256, 256>>>(likes_dst,   deg_photo, E1);
    degree_kernel<<<(E2 + 255) / 256, 256>>>(likedby_dst, deg_user,  E2);

    // Per-etype projection on tensor cores (tf32).
    gemm_tc<<<(N_USER  + 255) / 256, 256, SMEM_BYTES>>>(
        user_feats,  W_likes,   b_likes,   wh_user,  N_USER);
    gemm_tc<<<(N_PHOTO + 255) / 256, 256, SMEM_BYTES>>>(
        photo_feats, W_likedby, b_likedby, wh_photo, N_PHOTO);

    // Edge aggregation with mean folded in.
    {
        int h1 = (E1 + 1) >> 1;
        int h2 = (E2 + 1) >> 1;
        scatter_mean_kernel<<<((size_t)h1 * 16 + 255) / 256, 256>>>(
            wh_user,  likes_src,   likes_dst,   deg_photo, out_photo, E1);
        scatter_mean_kernel<<<((size_t)h2 * 16 + 255) / 256, 256>>>(
            wh_photo, likedby_src, likedby_dst, deg_user,  out_user,  E2);
    }
}

// round 4
// speedup vs baseline: 1.3088x; 1.0895x over previous
#include <cuda_runtime.h>
#include <cstdint>

#define N_USER  100000
#define N_PHOTO 200000
#define K_IN    256
#define N_OUT   64

typedef unsigned long long ull;

// Scratch (static device globals; no allocs).
__device__ float g_Wh_user [(size_t)N_USER  * N_OUT];   // 25.6 MB
__device__ float g_Wh_photo[(size_t)N_PHOTO * N_OUT];   // 51.2 MB
__device__ float g_deg_user [N_USER];
__device__ float g_deg_photo[N_PHOTO];
__device__ ull   g_Bpack_likes  [8192];                 // packed tf32 W (64 KB)
__device__ ull   g_Bpack_likedby[8192];

__device__ __forceinline__ unsigned f2tf32(float f) {
    unsigned r;
    asm("cvt.rna.tf32.f32 %0, %1;" : "=r"(r) : "f"(f));
    return r;
}

__device__ __forceinline__ void cp_async16(unsigned dst_smem, const void* src,
                                           unsigned src_bytes) {
    asm volatile("cp.async.cg.shared.global [%0], [%1], 16, %2;"
                 :: "r"(dst_smem), "l"(src), "r"(src_bytes) : "memory");
}

// ---------------------------------------------------------------------------
// Prepack W[256,64] -> fragment-ordered tf32 ull table:
//   index i = (kk*4 + t)*64 + slot, slot = jj*16 + g*2 + e
//   value   = pack( tf32 W[kk*8+t][n], tf32 W[kk*8+t+4][n] ), n = (2jj+e)*8 + g
// so a warp's B fragment for (kstep kk, thread group t, n-tile pair jj) is one
// bank-conflict-free LDS.128 at uint4 index (kk*4+t)*32 + jj*8 + g.
// ---------------------------------------------------------------------------
__global__ __launch_bounds__(256) void prepack_B(
    const float* __restrict__ W, ull* __restrict__ out)
{
    int i = blockIdx.x * 256 + threadIdx.x;      // 0..8191
    int kk = i >> 8, tt = (i >> 6) & 3, slot = i & 63;
    int jj = slot >> 4, g2 = (slot >> 1) & 7, e = slot & 1;
    int n  = (2 * jj + e) * 8 + g2;
    int k1 = kk * 8 + tt;
    unsigned lo = f2tf32(W[(size_t)k1 * 64 + n]);
    unsigned hi = f2tf32(W[(size_t)(k1 + 4) * 64 + n]);
    out[i] = ((ull)hi << 32) | (ull)lo;
}

// ---------------------------------------------------------------------------
// Tensor-core GEMM: C[M,64] = A[M,256] @ W[256,64] + bias  (tf32 HMMA)
// 256 threads, BM=128 rows; warp w owns m16 tile rows w*16..w*16+15, all 64 n.
// 4-stage cp.async pipeline streaming A chunks (128x32 fp32, padded rows) and
// prepacked B chunks (32k x 64n, fragment order). One barrier per chunk.
// ---------------------------------------------------------------------------
#define BM        128
#define STAGES    4
#define ASTRIDE   36                         // floats per padded A row
#define AS_STAGE  (BM * ASTRIDE)             // 4608 floats = 18 KB
#define BS_STAGE  1024                       // ulls = 8 KB
#define SMEM_A_BYTES (STAGES * AS_STAGE * 4) // 73728
#define SMEM_B_BYTES (STAGES * BS_STAGE * 8) // 32768
#define GEMM_SMEM    (SMEM_A_BYTES + SMEM_B_BYTES)  // 106496 (2 CTAs/SM)

__global__ __launch_bounds__(256, 2) void gemm_tc(
    const float* __restrict__ A, const ull* __restrict__ Bpack,
    const float* __restrict__ bias, float* __restrict__ C, int M)
{
    extern __shared__ char smem_raw[];
    float* As = (float*)smem_raw;
    ull*   Bs = (ull*)(smem_raw + SMEM_A_BYTES);
    const unsigned sA = (unsigned)__cvta_generic_to_shared(As);
    const unsigned sB = (unsigned)__cvta_generic_to_shared(Bs);

    const int tid  = threadIdx.x;
    const int lane = tid & 31;
    const int warp = tid >> 5;
    const int g = lane >> 2;          // 0..7
    const int t = lane & 3;           // 0..3
    const int rowBase = blockIdx.x * BM;

    const int segA = lane & 7;        // 16B segment within a row's 32-k chunk
    const int rA   = lane >> 3;       // row sub-index (+4*it)

    float acc[8][4];
#pragma unroll
    for (int j = 0; j < 8; j++)
#pragma unroll
        for (int q = 0; q < 4; q++) acc[j][q] = 0.f;

#define ISSUE_CHUNK(c, stage)                                                  \
    do {                                                                       \
        _Pragma("unroll")                                                      \
        for (int it = 0; it < 4; it++) {                                       \
            int rin  = warp * 16 + it * 4 + rA;                                \
            int grow = rowBase + rin;                                          \
            const float* srcp = A + (size_t)grow * K_IN + (c) * 32 + segA * 4; \
            unsigned sz  = (grow < M) ? 16u : 0u;                              \
            unsigned dst = sA + ((stage) * AS_STAGE + rin * ASTRIDE            \
                                 + segA * 4) * 4;                              \
            cp_async16(dst, srcp, sz);                                         \
        }                                                                      \
        _Pragma("unroll")                                                      \
        for (int j = 0; j < 2; j++) {                                          \
            int chunk = tid + j * 256;                                         \
            const ull* srcb = Bpack + (size_t)(c) * 1024 + chunk * 2;          \
            unsigned dst = sB + ((stage) * BS_STAGE + chunk * 2) * 8;          \
            cp_async16(dst, srcb, 16u);                                        \
        }                                                                      \
    } while (0)

    // prologue: stages 0..2
#pragma unroll
    for (int c = 0; c < 3; c++) {
        ISSUE_CHUNK(c, c);
        asm volatile("cp.async.commit_group;" ::: "memory");
    }

    for (int c = 0; c < 8; c++) {
        asm volatile("cp.async.wait_group 2;" ::: "memory");
        __syncthreads();                          // chunk c visible CTA-wide

        // refill the stage freed by chunk c-1 (all threads past compute(c-1))
        if (c + 3 < 8) ISSUE_CHUNK(c + 3, (c + 3) & 3);
        asm volatile("cp.async.commit_group;" ::: "memory");

        const int s = c & 3;
        const float* as = As + s * AS_STAGE + (warp * 16) * ASTRIDE;
        const uint4* bs = (const uint4*)(Bs + s * BS_STAGE);
#pragma unroll
        for (int kl = 0; kl < 4; kl++) {
            unsigned a0 = f2tf32(as[(g)     * ASTRIDE + kl * 8 + t]);
            unsigned a1 = f2tf32(as[(g + 8) * ASTRIDE + kl * 8 + t]);
            unsigned a2 = f2tf32(as[(g)     * ASTRIDE + kl * 8 + t + 4]);
            unsigned a3 = f2tf32(as[(g + 8) * ASTRIDE + kl * 8 + t + 4]);
            const uint4* bp = bs + (kl * 4 + t) * 32;
#pragma unroll
            for (int jj = 0; jj < 4; jj++) {
                uint4 bv = bp[jj * 8 + g];        // conflict-free LDS.128
                asm volatile(
                    "mma.sync.aligned.m16n8k8.row.col.f32.tf32.tf32.f32 "
                    "{%0,%1,%2,%3}, {%4,%5,%6,%7}, {%8,%9}, {%0,%1,%2,%3};"
                    : "+f"(acc[2 * jj][0]), "+f"(acc[2 * jj][1]),
                      "+f"(acc[2 * jj][2]), "+f"(acc[2 * jj][3])
                    : "r"(a0), "r"(a1), "r"(a2), "r"(a3),
                      "r"(bv.x), "r"(bv.y));
                asm volatile(
                    "mma.sync.aligned.m16n8k8.row.col.f32.tf32.tf32.f32 "
                    "{%0,%1,%2,%3}, {%4,%5,%6,%7}, {%8,%9}, {%0,%1,%2,%3};"
                    : "+f"(acc[2 * jj + 1][0]), "+f"(acc[2 * jj + 1][1]),
                      "+f"(acc[2 * jj + 1][2]), "+f"(acc[2 * jj + 1][3])
                    : "r"(a0), "r"(a1), "r"(a2), "r"(a3),
                      "r"(bv.z), "r"(bv.w));
            }
        }
    }

    // epilogue: bias + store (rows g, g+8 of this warp's m16 tile)
    int r0 = rowBase + warp * 16 + g;
#pragma unroll
    for (int j = 0; j < 8; j++) {
        int col = j * 8 + 2 * t;
        float b0 = __ldg(&bias[col]), b1 = __ldg(&bias[col + 1]);
        if (r0 < M)
            *(float2*)&C[(size_t)r0 * N_OUT + col] =
                make_float2(acc[j][0] + b0, acc[j][1] + b1);
        if (r0 + 8 < M)
            *(float2*)&C[(size_t)(r0 + 8) * N_OUT + col] =
                make_float2(acc[j][2] + b0, acc[j][3] + b1);
    }
#undef ISSUE_CHUNK
}

// ---------------------------------------------------------------------------
// In-degree accumulation (float counts).
// ---------------------------------------------------------------------------
__global__ __launch_bounds__(256) void degree_kernel(
    const int* __restrict__ dst, float* __restrict__ deg, int E)
{
    int e = blockIdx.x * 256 + threadIdx.x;
    if (e < E) atomicAdd(&deg[dst[e]], 1.0f);
}

// ---------------------------------------------------------------------------
// Edge scatter with mean folded in: out[d] += Wh[s] * (1/deg[d]).
// 16 threads per edge-lane, 2 edges per thread for MLP; vector REDs.
// ---------------------------------------------------------------------------
__global__ __launch_bounds__(256) void scatter_mean_kernel(
    const float* __restrict__ Wh, const int* __restrict__ src,
    const int* __restrict__ dst, const float* __restrict__ deg,
    float* __restrict__ out, int E)
{
    const int half = (E + 1) >> 1;
    int t = blockIdx.x * 256 + threadIdx.x;
    int e0 = t >> 4;
    if (e0 >= half) return;
    int lane = t & 15;
    int e1 = e0 + half;
    bool has1 = (e1 < E);

    int s0 = __ldg(&src[e0]);
    int d0 = __ldg(&dst[e0]);
    int s1 = has1 ? __ldg(&src[e1]) : s0;
    int d1 = has1 ? __ldg(&dst[e1]) : d0;

    float4 v0 = __ldg(((const float4*)(Wh + (size_t)s0 * N_OUT)) + lane);
    float4 v1 = __ldg(((const float4*)(Wh + (size_t)s1 * N_OUT)) + lane);
    float inv0 = __frcp_rn(__ldg(&deg[d0]));
    float inv1 = __frcp_rn(__ldg(&deg[d1]));

    v0.x *= inv0; v0.y *= inv0; v0.z *= inv0; v0.w *= inv0;
    float4* p0 = ((float4*)(out + (size_t)d0 * N_OUT)) + lane;
    asm volatile("red.global.add.v4.f32 [%0], {%1,%2,%3,%4};"
                 :: "l"(p0), "f"(v0.x), "f"(v0.y), "f"(v0.z), "f"(v0.w)
                 : "memory");
    if (has1) {
        v1.x *= inv1; v1.y *= inv1; v1.z *= inv1; v1.w *= inv1;
        float4* p1 = ((float4*)(out + (size_t)d1 * N_OUT)) + lane;
        asm volatile("red.global.add.v4.f32 [%0], {%1,%2,%3,%4};"
                     :: "l"(p1), "f"(v1.x), "f"(v1.y), "f"(v1.z), "f"(v1.w)
                     : "memory");
    }
}

// ---------------------------------------------------------------------------
extern "C" void kernel_launch(void* const* d_in, const int* in_sizes, int n_in,
                              void* d_out, int out_size)
{
    const float* user_feats  = (const float*)d_in[0];
    const float* photo_feats = (const float*)d_in[1];
    const float* W_likes     = (const float*)d_in[2];
    const float* b_likes     = (const float*)d_in[3];
    const float* W_likedby   = (const float*)d_in[4];
    const float* b_likedby   = (const float*)d_in[5];
    const int*   likes_src   = (const int*)d_in[6];
    const int*   likes_dst   = (const int*)d_in[7];
    const int*   likedby_src = (const int*)d_in[8];
    const int*   likedby_dst = (const int*)d_in[9];
    const int E1 = in_sizes[6];
    const int E2 = in_sizes[8];

    float* out_user  = (float*)d_out;                            // [N_USER, 64]
    float* out_photo = (float*)d_out + (size_t)N_USER * N_OUT;   // [N_PHOTO, 64]

    float *wh_user, *wh_photo, *deg_user, *deg_photo;
    ull *bp_likes, *bp_likedby;
    cudaGetSymbolAddress((void**)&wh_user,  g_Wh_user);
    cudaGetSymbolAddress((void**)&wh_photo, g_Wh_photo);
    cudaGetSymbolAddress((void**)&deg_user,  g_deg_user);
    cudaGetSymbolAddress((void**)&deg_photo, g_deg_photo);
    cudaGetSymbolAddress((void**)&bp_likes,   g_Bpack_likes);
    cudaGetSymbolAddress((void**)&bp_likedby, g_Bpack_likedby);

    cudaFuncSetAttribute(gemm_tc, cudaFuncAttributeMaxDynamicSharedMemorySize,
                         GEMM_SMEM);

    cudaMemsetAsync(d_out, 0, (size_t)out_size * sizeof(float));
    cudaMemsetAsync(deg_user,  0, (size_t)N_USER  * sizeof(float));
    cudaMemsetAsync(deg_photo, 0, (size_t)N_PHOTO * sizeof(float));

    // Weight prepack into MMA fragment order (tiny, L2-hot afterwards).
    prepack_B<<<32, 256>>>(W_likes,   bp_likes);
    prepack_B<<<32, 256>>>(W_likedby, bp_likedby);

    // Degrees (needed by the fused mean-scatter).
    degree_kernel<<<(E1 + 255) / 256, 256>>>(likes_dst,   deg_photo, E1);
    degree_kernel<<<(E2 + 255) / 256, 256>>>(likedby_dst, deg_user,  E2);

    // Per-etype projection on tensor cores (tf32, cp.async 4-stage pipeline).
    gemm_tc<<<(N_USER  + BM - 1) / BM, 256, GEMM_SMEM>>>(
        user_feats,  bp_likes,   b_likes,   wh_user,  N_USER);
    gemm_tc<<<(N_PHOTO + BM - 1) / BM, 256, GEMM_SMEM>>>(
        photo_feats, bp_likedby, b_likedby, wh_photo, N_PHOTO);

    // Edge aggregation with mean folded in.
    {
        int h1 = (E1 + 1) >> 1;
        int h2 = (E2 + 1) >> 1;
        scatter_mean_kernel<<<((size_t)h1 * 16 + 255) / 256, 256>>>(
            wh_user,  likes_src,   likes_dst,   deg_photo, out_photo, E1);
        scatter_mean_kernel<<<((size_t)h2 * 16 + 255) / 256, 256>>>(
            wh_photo, likedby_src, likedby_dst, deg_user,  out_user,  E2);
    }
}

// round 5
// speedup vs baseline: 1.8232x; 1.3930x over previous
#include <cuda_runtime.h>
#include <cstdint>

#define N_USER  100000
#define N_PHOTO 200000
#define K_IN    256
#define N_OUT   64

typedef unsigned long long ull;

// Scratch (static device globals; no allocs).
__device__ float g_Wh_user [(size_t)N_USER  * N_OUT];   // 25.6 MB
__device__ float g_Wh_photo[(size_t)N_PHOTO * N_OUT];   // 51.2 MB
__device__ float g_deg_user [N_USER];
__device__ float g_deg_photo[N_PHOTO];
__device__ ull   g_Bpack_likes  [8192];                 // packed tf32 W (64 KB)
__device__ ull   g_Bpack_likedby[8192];

__device__ __forceinline__ unsigned f2tf32(float f) {
    unsigned r;
    asm("cvt.rna.tf32.f32 %0, %1;" : "=r"(r) : "f"(f));
    return r;
}

__device__ __forceinline__ void cp_async16(unsigned dst_smem, const void* src,
                                           unsigned src_bytes) {
    asm volatile("cp.async.cg.shared.global [%0], [%1], 16, %2;"
                 :: "r"(dst_smem), "l"(src), "r"(src_bytes) : "memory");
}

// ---------------------------------------------------------------------------
// Prepack W[256,64] -> fragment-ordered tf32 ull table.
// ull index i: e = i&1; u = i>>1; t = u&3; g = (u>>2)&7; jj = (u>>5)&3; kk = u>>7.
// value = pack( tf32 W[kk*8+t][n], tf32 W[kk*8+t+4][n] ), n = (2jj+e)*8 + g.
// A warp's B fragment (kstep kk, quad t, n-pair jj) = one LDS.128 at uint4
// index kk*128 + jj*32 + g*4 + t  -> phase banks g*16+t*4: conflict-FREE.
// ---------------------------------------------------------------------------
__global__ __launch_bounds__(256) void prepack_B(
    const float* __restrict__ W, ull* __restrict__ out)
{
    int i = blockIdx.x * 256 + threadIdx.x;      // 0..8191
    int e = i & 1, u = i >> 1;
    int t = u & 3, g = (u >> 2) & 7, jj = (u >> 5) & 3, kk = u >> 7;
    int n  = (2 * jj + e) * 8 + g;
    int k1 = kk * 8 + t;
    unsigned lo = f2tf32(W[(size_t)k1 * 64 + n]);
    unsigned hi = f2tf32(W[(size_t)(k1 + 4) * 64 + n]);
    out[i] = ((ull)hi << 32) | (ull)lo;
}

// ---------------------------------------------------------------------------
// Tensor-core GEMM: C[M,64] = A[M,256] @ W[256,64] + bias  (tf32 HMMA)
// 256 threads, BM=256 rows; warp w owns rows w*32..w*32+31 (2 m16 tiles that
// SHARE B fragments). 3-stage cp.async pipeline (A 36KB + B 8KB per stage).
// ---------------------------------------------------------------------------
#define BM        256
#define STAGES    3
#define ASTRIDE   36                           // floats per padded A row
#define AS_STAGE  (BM * ASTRIDE)               // 9216 floats = 36 KB
#define BS_STAGE  1024                         // ulls = 8 KB
#define SMEM_A_BYTES (STAGES * AS_STAGE * 4)   // 110592
#define SMEM_B_BYTES (STAGES * BS_STAGE * 8)   // 24576
#define GEMM_SMEM    (SMEM_A_BYTES + SMEM_B_BYTES)

__global__ __launch_bounds__(256, 1) void gemm_tc(
    const float* __restrict__ A, const ull* __restrict__ Bpack,
    const float* __restrict__ bias, float* __restrict__ C, int M)
{
    extern __shared__ char smem_raw[];
    float* As = (float*)smem_raw;
    ull*   Bs = (ull*)(smem_raw + SMEM_A_BYTES);
    const unsigned sA = (unsigned)__cvta_generic_to_shared(As);
    const unsigned sB = (unsigned)__cvta_generic_to_shared(Bs);

    const int tid  = threadIdx.x;
    const int lane = tid & 31;
    const int warp = tid >> 5;
    const int g = lane >> 2;          // 0..7
    const int t = lane & 3;           // 0..3
    const int rowBase = blockIdx.x * BM;

    const int segA = lane & 7;        // 16B segment within a row's 32-k chunk
    const int rA   = lane >> 3;       // row sub-index (+4*it)

    float acc[2][8][4];
#pragma unroll
    for (int m = 0; m < 2; m++)
#pragma unroll
        for (int j = 0; j < 8; j++)
#pragma unroll
            for (int q = 0; q < 4; q++) acc[m][j][q] = 0.f;

#define ISSUE_CHUNK(c, stage)                                                  \
    do {                                                                       \
        _Pragma("unroll")                                                      \
        for (int it = 0; it < 8; it++) {                                       \
            int rin  = warp * 32 + it * 4 + rA;                                \
            int grow = rowBase + rin;                                          \
            const float* srcp = A + (size_t)grow * K_IN + (c) * 32 + segA * 4; \
            unsigned sz  = (grow < M) ? 16u : 0u;                              \
            unsigned dst = sA + ((stage) * AS_STAGE + rin * ASTRIDE            \
                                 + segA * 4) * 4;                              \
            cp_async16(dst, srcp, sz);                                         \
        }                                                                      \
        _Pragma("unroll")                                                      \
        for (int j = 0; j < 2; j++) {                                          \
            int chunk = tid + j * 256;                                         \
            const ull* srcb = Bpack + (size_t)(c) * 1024 + chunk * 2;          \
            unsigned dst = sB + ((stage) * BS_STAGE + chunk * 2) * 8;          \
            cp_async16(dst, srcb, 16u);                                        \
        }                                                                      \
    } while (0)

    // prologue: stages 0..1
    ISSUE_CHUNK(0, 0);
    asm volatile("cp.async.commit_group;" ::: "memory");
    ISSUE_CHUNK(1, 1);
    asm volatile("cp.async.commit_group;" ::: "memory");

    for (int c = 0; c < 8; c++) {
        asm volatile("cp.async.wait_group 1;" ::: "memory");
        __syncthreads();                          // chunk c visible CTA-wide

        if (c + 2 < 8) {
            int st = (c + 2) % STAGES;
            ISSUE_CHUNK(c + 2, st);
        }
        asm volatile("cp.async.commit_group;" ::: "memory");

        const int s = c % STAGES;
        const float* as = As + s * AS_STAGE + (warp * 32) * ASTRIDE;
        const uint4* bs = (const uint4*)(Bs + s * BS_STAGE);
#pragma unroll
        for (int kl = 0; kl < 4; kl++) {
            uint4 bv[4];
#pragma unroll
            for (int jj = 0; jj < 4; jj++)
                bv[jj] = bs[kl * 128 + jj * 32 + g * 4 + t];   // conflict-free
#pragma unroll
            for (int m = 0; m < 2; m++) {
                const float* am = as + m * 16 * ASTRIDE;
                unsigned a0 = f2tf32(am[(g)     * ASTRIDE + kl * 8 + t]);
                unsigned a1 = f2tf32(am[(g + 8) * ASTRIDE + kl * 8 + t]);
                unsigned a2 = f2tf32(am[(g)     * ASTRIDE + kl * 8 + t + 4]);
                unsigned a3 = f2tf32(am[(g + 8) * ASTRIDE + kl * 8 + t + 4]);
#pragma unroll
                for (int jj = 0; jj < 4; jj++) {
                    asm volatile(
                        "mma.sync.aligned.m16n8k8.row.col.f32.tf32.tf32.f32 "
                        "{%0,%1,%2,%3}, {%4,%5,%6,%7}, {%8,%9}, {%0,%1,%2,%3};"
                        : "+f"(acc[m][2 * jj][0]), "+f"(acc[m][2 * jj][1]),
                          "+f"(acc[m][2 * jj][2]), "+f"(acc[m][2 * jj][3])
                        : "r"(a0), "r"(a1), "r"(a2), "r"(a3),
                          "r"(bv[jj].x), "r"(bv[jj].y));
                    asm volatile(
                        "mma.sync.aligned.m16n8k8.row.col.f32.tf32.tf32.f32 "
                        "{%0,%1,%2,%3}, {%4,%5,%6,%7}, {%8,%9}, {%0,%1,%2,%3};"
                        : "+f"(acc[m][2 * jj + 1][0]), "+f"(acc[m][2 * jj + 1][1]),
                          "+f"(acc[m][2 * jj + 1][2]), "+f"(acc[m][2 * jj + 1][3])
                        : "r"(a0), "r"(a1), "r"(a2), "r"(a3),
                          "r"(bv[jj].z), "r"(bv[jj].w));
                }
            }
        }
    }

    // epilogue: bias + store
#pragma unroll
    for (int m = 0; m < 2; m++) {
        int r0 = rowBase + warp * 32 + m * 16 + g;
#pragma unroll
        for (int j = 0; j < 8; j++) {
            int col = j * 8 + 2 * t;
            float b0 = __ldg(&bias[col]), b1 = __ldg(&bias[col + 1]);
            if (r0 < M)
                *(float2*)&C[(size_t)r0 * N_OUT + col] =
                    make_float2(acc[m][j][0] + b0, acc[m][j][1] + b1);
            if (r0 + 8 < M)
                *(float2*)&C[(size_t)(r0 + 8) * N_OUT + col] =
                    make_float2(acc[m][j][2] + b0, acc[m][j][3] + b1);
        }
    }
#undef ISSUE_CHUNK
}

// ---------------------------------------------------------------------------
// In-degree accumulation, 4 edges per thread (int4 load + 4 REDs in flight).
// ---------------------------------------------------------------------------
__global__ __launch_bounds__(256) void degree_kernel(
    const int* __restrict__ dst, float* __restrict__ deg, int E)
{
    int base = (blockIdx.x * 256 + threadIdx.x) * 4;
    if (base + 3 < E) {
        int4 d = *(const int4*)(dst + base);
        atomicAdd(&deg[d.x], 1.0f);
        atomicAdd(&deg[d.y], 1.0f);
        atomicAdd(&deg[d.z], 1.0f);
        atomicAdd(&deg[d.w], 1.0f);
    } else {
        for (int e = base; e < E; e++) atomicAdd(&deg[dst[e]], 1.0f);
    }
}

// ---------------------------------------------------------------------------
// Edge scatter with mean folded in: out[d] += Wh[s] * (1/deg[d]).
// 16 threads per edge-lane, 4 edges per thread (4 independent gather+RED
// chains in flight against L2 latency).
// ---------------------------------------------------------------------------
__global__ __launch_bounds__(256) void scatter_mean_kernel(
    const float* __restrict__ Wh, const int* __restrict__ src,
    const int* __restrict__ dst, const float* __restrict__ deg,
    float* __restrict__ out, int E)
{
    const int quarter = (E + 3) >> 2;
    int t = blockIdx.x * 256 + threadIdx.x;
    int e0 = t >> 4;
    if (e0 >= quarter) return;
    int lane = t & 15;

    int    ei[4];
    bool   has[4];
    int    s_[4], d_[4];
#pragma unroll
    for (int i = 0; i < 4; i++) {
        ei[i]  = e0 + i * quarter;
        has[i] = ei[i] < E;
        s_[i]  = has[i] ? __ldg(&src[ei[i]]) : 0;
        d_[i]  = has[i] ? __ldg(&dst[ei[i]]) : 0;
    }
    float4 v[4];
    float  inv[4];
#pragma unroll
    for (int i = 0; i < 4; i++) {
        if (has[i]) {
            v[i]   = __ldg(((const float4*)(Wh + (size_t)s_[i] * N_OUT)) + lane);
            inv[i] = __frcp_rn(__ldg(&deg[d_[i]]));
        }
    }
#pragma unroll
    for (int i = 0; i < 4; i++) {
        if (has[i]) {
            float4 w = v[i];
            w.x *= inv[i]; w.y *= inv[i]; w.z *= inv[i]; w.w *= inv[i];
            float4* p = ((float4*)(out + (size_t)d_[i] * N_OUT)) + lane;
            asm volatile("red.global.add.v4.f32 [%0], {%1,%2,%3,%4};"
                         :: "l"(p), "f"(w.x), "f"(w.y), "f"(w.z), "f"(w.w)
                         : "memory");
        }
    }
}

// ---------------------------------------------------------------------------
extern "C" void kernel_launch(void* const* d_in, const int* in_sizes, int n_in,
                              void* d_out, int out_size)
{
    const float* user_feats  = (const float*)d_in[0];
    const float* photo_feats = (const float*)d_in[1];
    const float* W_likes     = (const float*)d_in[2];
    const float* b_likes     = (const float*)d_in[3];
    const float* W_likedby   = (const float*)d_in[4];
    const float* b_likedby   = (const float*)d_in[5];
    const int*   likes_src   = (const int*)d_in[6];
    const int*   likes_dst   = (const int*)d_in[7];
    const int*   likedby_src = (const int*)d_in[8];
    const int*   likedby_dst = (const int*)d_in[9];
    const int E1 = in_sizes[6];
    const int E2 = in_sizes[8];

    float* out_user  = (float*)d_out;                            // [N_USER, 64]
    float* out_photo = (float*)d_out + (size_t)N_USER * N_OUT;   // [N_PHOTO, 64]

    float *wh_user, *wh_photo, *deg_user, *deg_photo;
    ull *bp_likes, *bp_likedby;
    cudaGetSymbolAddress((void**)&wh_user,  g_Wh_user);
    cudaGetSymbolAddress((void**)&wh_photo, g_Wh_photo);
    cudaGetSymbolAddress((void**)&deg_user,  g_deg_user);
    cudaGetSymbolAddress((void**)&deg_photo, g_deg_photo);
    cudaGetSymbolAddress((void**)&bp_likes,   g_Bpack_likes);
    cudaGetSymbolAddress((void**)&bp_likedby, g_Bpack_likedby);

    // One-time setup (first call is the uncaptured correctness run).
    static cudaStream_t s_aux = nullptr, s_sc = nullptr;
    static cudaEvent_t evStart, evAux, evG1, evSc1;
    if (!s_aux) {
        cudaStreamCreateWithFlags(&s_aux, cudaStreamNonBlocking);
        cudaStreamCreateWithFlags(&s_sc,  cudaStreamNonBlocking);
        cudaEventCreateWithFlags(&evStart, cudaEventDisableTiming);
        cudaEventCreateWithFlags(&evAux,   cudaEventDisableTiming);
        cudaEventCreateWithFlags(&evG1,    cudaEventDisableTiming);
        cudaEventCreateWithFlags(&evSc1,   cudaEventDisableTiming);
        cudaFuncSetAttribute(gemm_tc,
                             cudaFuncAttributeMaxDynamicSharedMemorySize,
                             GEMM_SMEM);
    }

    // Fork aux stream off the capture (main) stream.
    cudaEventRecord(evStart, 0);
    cudaStreamWaitEvent(s_aux, evStart, 0);

    // Aux path: zeroing + degrees (independent of the GEMMs).
    cudaMemsetAsync(d_out, 0, (size_t)out_size * sizeof(float), s_aux);
    cudaMemsetAsync(deg_user,  0, (size_t)N_USER  * sizeof(float), s_aux);
    cudaMemsetAsync(deg_photo, 0, (size_t)N_PHOTO * sizeof(float), s_aux);
    degree_kernel<<<(E1 / 4 + 256) / 256 + 1, 256, 0, s_aux>>>(likes_dst,   deg_photo, E1);
    degree_kernel<<<(E2 / 4 + 256) / 256 + 1, 256, 0, s_aux>>>(likedby_dst, deg_user,  E2);
    cudaEventRecord(evAux, s_aux);

    // Main path: prepack + the two projections.
    prepack_B<<<32, 256>>>(W_likes,   bp_likes);
    prepack_B<<<32, 256>>>(W_likedby, bp_likedby);
    gemm_tc<<<(N_USER + BM - 1) / BM, 256, GEMM_SMEM>>>(
        user_feats,  bp_likes,   b_likes,   wh_user,  N_USER);
    cudaEventRecord(evG1, 0);
    gemm_tc<<<(N_PHOTO + BM - 1) / BM, 256, GEMM_SMEM>>>(
        photo_feats, bp_likedby, b_likedby, wh_photo, N_PHOTO);

    // scatter1 (photo outputs) overlaps gemm_photo on its own stream.
    cudaStreamWaitEvent(s_sc, evG1, 0);
    cudaStreamWaitEvent(s_sc, evAux, 0);
    {
        int q1 = (E1 + 3) >> 2;
        scatter_mean_kernel<<<((size_t)q1 * 16 + 255) / 256, 256, 0, s_sc>>>(
            wh_user, likes_src, likes_dst, deg_photo, out_photo, E1);
    }
    cudaEventRecord(evSc1, s_sc);

    // scatter2 (user outputs) on the main stream after gemm_photo.
    cudaStreamWaitEvent(0, evAux, 0);
    {
        int q2 = (E2 + 3) >> 2;
        scatter_mean_kernel<<<((size_t)q2 * 16 + 255) / 256, 256>>>(
            wh_photo, likedby_src, likedby_dst, deg_user, out_user, E2);
    }

    // Join everything back onto the capture stream.
    cudaStreamWaitEvent(0, evSc1, 0);
}